// round 3
// baseline (speedup 1.0000x reference)
#include <cuda_runtime.h>
#include <cuda_bf16.h>
#include <cstdint>

// LJ constants (match reference); sigma=1, cutoff=5
#define EPSILON 1.0f
#define SHIFT_F (4.0f * (1.0f/244140625.0f - 1.0f/15625.0f))

__global__ void lj_zero_kernel(float* __restrict__ out, int n) {
    int i = blockIdx.x * blockDim.x + threadIdx.x;
    if (i < n) out[i] = 0.0f;
}

__device__ __forceinline__ float lj_half_e(float x, float y, float z) {
    float r2   = fmaf(x, x, fmaf(y, y, z * z));
    float inv2 = 1.0f / r2;
    float sr6  = inv2 * inv2 * inv2;
    float e    = 4.0f * EPSILON * fmaf(sr6, sr6, -sr6) - SHIFT_F;
    return 0.5f * e;
}

// 4 edges per thread: 3x float4 + 2x int4 loads, 8 REDs.
__global__ void __launch_bounds__(256)
lj_edge_kernel_v4(const float4* __restrict__ dist4,   // [E/4 * 3] float4 view
                  const int4*   __restrict__ atom_a4,
                  const int4*   __restrict__ atom_b4,
                  float* __restrict__ out,
                  int n_quads) {
    int t = blockIdx.x * blockDim.x + threadIdx.x;
    if (t >= n_quads) return;

    // Indices first: get them in flight.
    int4 ia = atom_a4[t];
    int4 ib = atom_b4[t];

    // 4 edges = 12 floats = 3 float4 (48 contiguous bytes per thread).
    float4 d0 = dist4[3 * t + 0];   // e0.xyz, e1.x
    float4 d1 = dist4[3 * t + 1];   // e1.yz,  e2.xy
    float4 d2 = dist4[3 * t + 2];   // e2.z,   e3.xyz

    float h0 = lj_half_e(d0.x, d0.y, d0.z);
    float h1 = lj_half_e(d0.w, d1.x, d1.y);
    float h2 = lj_half_e(d1.z, d1.w, d2.x);
    float h3 = lj_half_e(d2.y, d2.z, d2.w);

    // fire-and-forget -> RED.ADD
    atomicAdd(out + ia.x, h0);
    atomicAdd(out + ib.x, h0);
    atomicAdd(out + ia.y, h1);
    atomicAdd(out + ib.y, h1);
    atomicAdd(out + ia.z, h2);
    atomicAdd(out + ib.z, h2);
    atomicAdd(out + ia.w, h3);
    atomicAdd(out + ib.w, h3);
}

// Scalar tail for n_edges % 4 != 0 (defensive; E=6.4M is divisible by 4).
__global__ void lj_edge_tail(const float* __restrict__ dist,
                             const int* __restrict__ atom_a,
                             const int* __restrict__ atom_b,
                             float* __restrict__ out,
                             int start, int n_edges) {
    int i = start + blockIdx.x * blockDim.x + threadIdx.x;
    if (i >= n_edges) return;
    float h = lj_half_e(dist[3*i], dist[3*i+1], dist[3*i+2]);
    atomicAdd(out + atom_a[i], h);
    atomicAdd(out + atom_b[i], h);
}

extern "C" void kernel_launch(void* const* d_in, const int* in_sizes, int n_in,
                              void* d_out, int out_size) {
    const float* dist   = (const float*)d_in[0];
    const int*   atom_a = (const int*)d_in[1];   // JAX x64-disabled: int32
    const int*   atom_b = (const int*)d_in[2];
    float* out = (float*)d_out;

    int n_edges = in_sizes[1];
    int n_atoms = out_size;

    {
        int threads = 256;
        int blocks = (n_atoms + threads - 1) / threads;
        lj_zero_kernel<<<blocks, threads>>>(out, n_atoms);
    }

    int n_quads = n_edges / 4;
    if (n_quads > 0) {
        int threads = 256;
        int blocks = (n_quads + threads - 1) / threads;
        lj_edge_kernel_v4<<<blocks, threads>>>(
            (const float4*)dist, (const int4*)atom_a, (const int4*)atom_b,
            out, n_quads);
    }
    int done = n_quads * 4;
    if (done < n_edges) {
        int rem = n_edges - done;
        int threads = 256;
        int blocks = (rem + threads - 1) / threads;
        lj_edge_tail<<<blocks, threads>>>(dist, atom_a, atom_b, out, done, n_edges);
    }
}

// round 4
// speedup vs baseline: 1.0517x; 1.0517x over previous
#include <cuda_runtime.h>
#include <cuda_bf16.h>
#include <cstdint>

// LJ constants (match reference); sigma=1, cutoff=5
#define EPSILON 1.0f
#define SHIFT_F (4.0f * (1.0f/244140625.0f - 1.0f/15625.0f))

// Replicated accumulation scratch: R copies of the output, L2-resident.
// 16 * (100000+128) floats = 6.41 MB static device memory (no dynamic alloc).
#define NREP 16
#define MAX_ATOMS 100000
#define REP_STRIDE (MAX_ATOMS + 128)
__device__ float g_scratch[NREP * REP_STRIDE];

__global__ void lj_zero_scratch(int total) {
    int i = blockIdx.x * blockDim.x + threadIdx.x;
    if (i < total) g_scratch[i] = 0.0f;
}

__device__ __forceinline__ float lj_half_e(float x, float y, float z) {
    float r2   = fmaf(x, x, fmaf(y, y, z * z));
    float inv2 = 1.0f / r2;
    float sr6  = inv2 * inv2 * inv2;
    float e    = 4.0f * EPSILON * fmaf(sr6, sr6, -sr6) - SHIFT_F;
    return 0.5f * e;
}

// Scalar 1-edge/thread (best mainloop so far) + replica-spread atomics.
__global__ void __launch_bounds__(256)
lj_edge_kernel_rep(const float* __restrict__ dist,
                   const int* __restrict__ atom_a,
                   const int* __restrict__ atom_b,
                   int n_edges) {
    int i = blockIdx.x * blockDim.x + threadIdx.x;
    if (i >= n_edges) return;

    float x = dist[3 * i + 0];
    float y = dist[3 * i + 1];
    float z = dist[3 * i + 2];
    float h = lj_half_e(x, y, z);

    int ia = atom_a[i];
    int ib = atom_b[i];

    // Per-thread replica: drops per-address concurrency & per-sector op
    // density by NREP; spreads ops across NREP x more LTS sectors.
    float* rep = g_scratch + (i & (NREP - 1)) * REP_STRIDE;
    atomicAdd(rep + ia, h);   // RED.ADD, fire-and-forget
    atomicAdd(rep + ib, h);
}

// Fallback path (atom count exceeds static scratch): direct atomics into out.
__global__ void lj_zero_out(float* __restrict__ out, int n) {
    int i = blockIdx.x * blockDim.x + threadIdx.x;
    if (i < n) out[i] = 0.0f;
}
__global__ void lj_edge_kernel_direct(const float* __restrict__ dist,
                                      const int* __restrict__ atom_a,
                                      const int* __restrict__ atom_b,
                                      float* __restrict__ out,
                                      int n_edges) {
    int i = blockIdx.x * blockDim.x + threadIdx.x;
    if (i >= n_edges) return;
    float h = lj_half_e(dist[3*i], dist[3*i+1], dist[3*i+2]);
    atomicAdd(out + atom_a[i], h);
    atomicAdd(out + atom_b[i], h);
}

// Reduce R replicas -> out.
__global__ void lj_reduce_kernel(float* __restrict__ out, int n_atoms) {
    int i = blockIdx.x * blockDim.x + threadIdx.x;
    if (i >= n_atoms) return;
    float s = 0.0f;
    #pragma unroll
    for (int r = 0; r < NREP; r++)
        s += g_scratch[r * REP_STRIDE + i];
    out[i] = s;
}

extern "C" void kernel_launch(void* const* d_in, const int* in_sizes, int n_in,
                              void* d_out, int out_size) {
    const float* dist   = (const float*)d_in[0];
    const int*   atom_a = (const int*)d_in[1];   // JAX x64-disabled: int32
    const int*   atom_b = (const int*)d_in[2];
    float* out = (float*)d_out;

    int n_edges = in_sizes[1];
    int n_atoms = out_size;
    const int T = 256;

    if (n_atoms <= MAX_ATOMS) {
        int total = NREP * REP_STRIDE;
        lj_zero_scratch<<<(total + T - 1) / T, T>>>(total);
        lj_edge_kernel_rep<<<(n_edges + T - 1) / T, T>>>(dist, atom_a, atom_b, n_edges);
        lj_reduce_kernel<<<(n_atoms + T - 1) / T, T>>>(out, n_atoms);
    } else {
        lj_zero_out<<<(n_atoms + T - 1) / T, T>>>(out, n_atoms);
        lj_edge_kernel_direct<<<(n_edges + T - 1) / T, T>>>(dist, atom_a, atom_b, out, n_edges);
    }
}